// round 15
// baseline (speedup 1.0000x reference)
#include <cuda_runtime.h>
#include <cstdint>

#define HDIM   512
#define TLEN   2048
#define NBATCH 16
#define CLSZ   8
#define NCLUSTER (NBATCH / 2)       // 8 scan clusters, 2 batches each
#define NTHREADS 640                // 16 producer warps + 4 finisher warps
#define BARCNT   576                // 512 producers + 64 finisher threads
#define SCAN_CTAS (NCLUSTER * CLSZ) // 64
#define GEMM_CTAS 2048              // 16 batches x 16 t-chunks x 8 n-blocks
#define GRID (SCAN_CTAS + GEMM_CTAS)

typedef unsigned long long u64;
typedef unsigned int u32;

// chunk-completion flags: g_flags[b*16+c] counts finished n-blocks (ready at 8).
// zero-initialized at module load; scan resets its batches' flags at kernel end
// so every graph replay starts from zero.
__device__ int g_flags[NBATCH * 16];

// ---------------- PTX helpers ----------------
__device__ __forceinline__ u32 smem_u32(const void* p) {
    u32 a;
    asm("{ .reg .u64 t; cvta.to.shared.u64 t, %1; cvt.u32.u64 %0, t; }" : "=r"(a) : "l"(p));
    return a;
}
__device__ __forceinline__ void fma2(u64& d, u64 a, u64 b) {
    asm("fma.rn.f32x2 %0, %1, %2, %0;" : "+l"(d) : "l"(a), "l"(b));
}
__device__ __forceinline__ u64 pk2(float lo, float hi) {
    u64 r; asm("mov.b64 %0, {%1, %2};" : "=l"(r) : "f"(lo), "f"(hi)); return r;
}
__device__ __forceinline__ float lo32(u64 v) { return __uint_as_float((u32)(v & 0xffffffffull)); }
__device__ __forceinline__ float hi32(u64 v) { return __uint_as_float((u32)(v >> 32)); }
__device__ __forceinline__ u32 mapa32(u32 a, u32 r) {
    u32 d; asm("mapa.shared::cluster.u32 %0, %1, %2;" : "=r"(d) : "r"(a), "r"(r)); return d;
}
__device__ __forceinline__ void st_async32(u32 ra, u32 v, u32 rb) {
    asm volatile("st.async.shared::cluster.mbarrier::complete_tx::bytes.b32 [%0], %1, [%2];"
                 :: "r"(ra), "r"(v), "r"(rb) : "memory");
}
__device__ __forceinline__ void mbar_init(u32 m, u32 cnt) {
    asm volatile("mbarrier.init.shared.b64 [%0], %1;" :: "r"(m), "r"(cnt) : "memory");
}
__device__ __forceinline__ void mbar_expect_tx(u32 m, u32 bytes) {
    asm volatile("mbarrier.arrive.expect_tx.shared.b64 _, [%0], %1;" :: "r"(m), "r"(bytes) : "memory");
}
__device__ __forceinline__ void mbar_wait_parity(u32 m, u32 parity) {
    asm volatile(
        "{\n\t.reg .pred P;\nLW_%=:\n\t"
        "mbarrier.try_wait.parity.acquire.cluster.shared::cta.b64 P, [%0], %1, 0x989680;\n\t"
        "@!P bra LW_%=;\n\t}"
        :: "r"(m), "r"(parity) : "memory");
}
__device__ __forceinline__ void cluster_sync_() {
    asm volatile("barrier.cluster.arrive.aligned;" ::: "memory");
    asm volatile("barrier.cluster.wait.aligned;" ::: "memory");
}
__device__ __forceinline__ void bar_arrive(int id) {
    asm volatile("bar.arrive %0, %1;" :: "r"(id), "r"(BARCNT) : "memory");
}
__device__ __forceinline__ void bar_sync_named(int id) {
    asm volatile("bar.sync %0, %1;" :: "r"(id), "r"(BARCNT) : "memory");
}
__device__ __forceinline__ int ld_acq(const int* p) {
    int v;
    asm volatile("ld.acquire.gpu.global.b32 %0, [%1];" : "=r"(v) : "l"(p) : "memory");
    return v;
}
// tanh(x) = sign(x)*(1-e)/(1+e), e = exp2(-2x*log2e), ~1e-7 abs err
__device__ __forceinline__ float fast_tanh(float x) {
    float ax = fabsf(x);
    float e;
    asm("ex2.approx.ftz.f32 %0, %1;" : "=f"(e) : "f"(ax * -2.885390082f));
    float r;
    asm("rcp.approx.ftz.f32 %0, %1;" : "=f"(r) : "f"(1.0f + e));
    return copysignf((1.0f - e) * r, x);
}

// ---------------- fused kernel ----------------
// blocks 0..63      : scan clusters (exact R14 structure + chunk-flag gating)
// blocks 64..2111   : GEMM pre = X @ W_xh + b, one 128x64 tile per block,
//                     chunk-major order so early timesteps finish first.
__global__ __launch_bounds__(NTHREADS, 1) __cluster_dims__(CLSZ, 1, 1)
void fused_rnn(const float* __restrict__ X, const float* __restrict__ Wxh,
               const float* __restrict__ bias, const float* __restrict__ Whh,
               float* __restrict__ out)
{
    // ---- shared memory (scan set + gemm set; disjoint CTA roles) ----
    __shared__ __align__(16) float hA[2][HDIM];
    __shared__ __align__(16) float hB[2][HDIM];
    __shared__ __align__(16) float redA[16][64];
    __shared__ __align__(16) float redB[16][64];
    __shared__ __align__(16) u64 mbar[4];
    __shared__ __align__(16) float As[16][130];
    __shared__ __align__(16) float Bs[16][64];

    const int tid = threadIdx.x;

    if (blockIdx.x >= SCAN_CTAS) {
        // ================= GEMM path =================
        const int gid = blockIdx.x - SCAN_CTAS;
        const int n0  = (gid & 7) * 64;
        const int bb  = (gid >> 3) & 15;     // batch
        const int cc  = gid >> 7;            // t-chunk (0..15) — chunk-major order
        const int m0  = bb * 2048 + cc * 128;

        const int tx = tid & 15;
        const int ty = tid >> 4;             // valid for tid < 512

        float acc[4][4];
        #pragma unroll
        for (int i = 0; i < 4; i++)
            #pragma unroll
            for (int j = 0; j < 4; j++) acc[i][j] = 0.0f;

        for (int kb = 0; kb < 32; kb++) {
            const int k0 = kb * 16;
            if (tid < 512) {
                const int arow = tid >> 2;
                const int akq  = (tid & 3) * 4;
                float4 a = *(const float4*)(X + (long)(m0 + arow) * HDIM + k0 + akq);
                As[akq+0][arow] = a.x; As[akq+1][arow] = a.y;
                As[akq+2][arow] = a.z; As[akq+3][arow] = a.w;
            }
            if (tid < 256) {
                const int bk = tid >> 4;
                const int bn = (tid & 15) * 4;
                *(float4*)&Bs[bk][bn] = *(const float4*)(Wxh + (long)(k0 + bk) * HDIM + n0 + bn);
            }
            __syncthreads();
            if (tid < 512) {
                #pragma unroll
                for (int k = 0; k < 16; k++) {
                    float4 rb = *(const float4*)&Bs[k][tx * 4];
                    float2 r0 = *(const float2*)&As[k][ty * 4];
                    float2 r1 = *(const float2*)&As[k][ty * 4 + 2];
                    float ra[4] = { r0.x, r0.y, r1.x, r1.y };
                    #pragma unroll
                    for (int i = 0; i < 4; i++) {
                        acc[i][0] += ra[i] * rb.x;
                        acc[i][1] += ra[i] * rb.y;
                        acc[i][2] += ra[i] * rb.z;
                        acc[i][3] += ra[i] * rb.w;
                    }
                }
            }
            __syncthreads();
        }
        if (tid < 512) {
            float4 bb4 = *(const float4*)(bias + n0 + tx * 4);
            #pragma unroll
            for (int i = 0; i < 4; i++) {
                float4 o;
                o.x = acc[i][0] + bb4.x; o.y = acc[i][1] + bb4.y;
                o.z = acc[i][2] + bb4.z; o.w = acc[i][3] + bb4.w;
                *(float4*)&out[(long)(m0 + ty * 4 + i) * HDIM + n0 + tx * 4] = o;
            }
        }
        __threadfence();
        __syncthreads();
        if (tid == 0) atomicAdd(&g_flags[bb * 16 + cc], 1);
        return;
    }

    // ================= scan path (R14 + flag gating) =================
    const int wi   = tid >> 5;
    const int lane = tid & 31;
    const int rank = blockIdx.x & (CLSZ - 1);
    const int cl   = blockIdx.x / CLSZ;

    for (int i = tid; i < 2 * HDIM; i += NTHREADS) {
        ((float*)hA)[i] = 0.0f;
        ((float*)hB)[i] = 0.0f;
    }
    const u32 hAa = smem_u32(&hA[0][0]);
    const u32 hBa = smem_u32(&hB[0][0]);
    const u32 mb0 = smem_u32(&mbar[0]);
    if (tid == 0) {
        mbar_init(mb0,      1);
        mbar_init(mb0 + 8,  1);
        mbar_init(mb0 + 16, 1);
        mbar_init(mb0 + 24, 1);
        asm volatile("fence.mbarrier_init.release.cluster;" ::: "memory");
    }
    __syncthreads();
    cluster_sync_();

    const long baseA = (long)(2 * cl)     * TLEN * HDIM + rank * 64;
    const long baseB = (long)(2 * cl + 1) * TLEN * HDIM + rank * 64;

    if (wi < 16) {
        // ---- producers ----
        const int jg = tid & 15;
        const int kc = tid >> 4;
        u64 w[4][8];
        {
            const int j0 = rank * 64 + jg * 4;
            const int kb = kc * 16;
            #pragma unroll
            for (int p = 0; p < 8; p++) {
                float4 l4 = *(const float4*)(Whh + (kb + 2*p)     * HDIM + j0);
                float4 h4 = *(const float4*)(Whh + (kb + 2*p + 1) * HDIM + j0);
                w[0][p] = pk2(l4.x, h4.x);
                w[1][p] = pk2(l4.y, h4.y);
                w[2][p] = pk2(l4.z, h4.z);
                w[3][p] = pk2(l4.w, h4.w);
            }
        }
        for (int t = 0; t < TLEN; ++t) {
            const int pb = t & 1;
            const u32 par = (u32)(((t - 2 + pb) >> 1) & 1);

            if (t > 0) mbar_wait_parity(mb0 + (u32)pb * 8u, par);      // A ready
            {
                const ulonglong2* hp = (const ulonglong2*)&hA[pb][kc * 16];
                u64 a0 = 0ull, a1 = 0ull, a2 = 0ull, a3 = 0ull;
                #pragma unroll
                for (int p = 0; p < 4; p++) {
                    ulonglong2 hv = hp[p];
                    fma2(a0, hv.x, w[0][2*p]);   fma2(a1, hv.x, w[1][2*p]);
                    fma2(a2, hv.x, w[2][2*p]);   fma2(a3, hv.x, w[3][2*p]);
                    fma2(a0, hv.y, w[0][2*p+1]); fma2(a1, hv.y, w[1][2*p+1]);
                    fma2(a2, hv.y, w[2][2*p+1]); fma2(a3, hv.y, w[3][2*p+1]);
                }
                float s0 = lo32(a0) + hi32(a0);
                float s1 = lo32(a1) + hi32(a1);
                float s2 = lo32(a2) + hi32(a2);
                float s3 = lo32(a3) + hi32(a3);
                s0 += __shfl_down_sync(0xffffffffu, s0, 16);
                s1 += __shfl_down_sync(0xffffffffu, s1, 16);
                s2 += __shfl_down_sync(0xffffffffu, s2, 16);
                s3 += __shfl_down_sync(0xffffffffu, s3, 16);
                if (lane < 16) {
                    float4 v; v.x = s0; v.y = s1; v.z = s2; v.w = s3;
                    *(float4*)&redA[wi][jg * 4] = v;
                }
            }
            bar_arrive(1);

            if (t > 0) mbar_wait_parity(mb0 + 16u + (u32)pb * 8u, par); // B ready
            {
                const ulonglong2* hp = (const ulonglong2*)&hB[pb][kc * 16];
                u64 a0 = 0ull, a1 = 0ull, a2 = 0ull, a3 = 0ull;
                #pragma unroll
                for (int p = 0; p < 4; p++) {
                    ulonglong2 hv = hp[p];
                    fma2(a0, hv.x, w[0][2*p]);   fma2(a1, hv.x, w[1][2*p]);
                    fma2(a2, hv.x, w[2][2*p]);   fma2(a3, hv.x, w[3][2*p]);
                    fma2(a0, hv.y, w[0][2*p+1]); fma2(a1, hv.y, w[1][2*p+1]);
                    fma2(a2, hv.y, w[2][2*p+1]); fma2(a3, hv.y, w[3][2*p+1]);
                }
                float s0 = lo32(a0) + hi32(a0);
                float s1 = lo32(a1) + hi32(a1);
                float s2 = lo32(a2) + hi32(a2);
                float s3 = lo32(a3) + hi32(a3);
                s0 += __shfl_down_sync(0xffffffffu, s0, 16);
                s1 += __shfl_down_sync(0xffffffffu, s1, 16);
                s2 += __shfl_down_sync(0xffffffffu, s2, 16);
                s3 += __shfl_down_sync(0xffffffffu, s3, 16);
                if (lane < 16) {
                    float4 v; v.x = s0; v.y = s1; v.z = s2; v.w = s3;
                    *(float4*)&redB[wi][jg * 4] = v;
                }
            }
            bar_arrive(2);
        }
    } else {
        // ---- finishers ----
        const int wf    = wi - 16;          // 0,1 = batch A; 2,3 = batch B
        const int isB   = wf >> 1;
        const long base = isB ? baseB : baseA;
        const u32 hXa   = isB ? hBa : hAa;
        const u32 mbX   = mb0 + (isB ? 16u : 0u);
        const int barid = isB ? 2 : 1;
        const float* red = isB ? &redB[0][0] : &redA[0][0];
        const int col   = (wf & 1) * 32 + lane;
        const int doExpect = ((wf & 1) == 0) && (lane == 0);
        const int* flg  = &g_flags[(2 * cl + isB) * 16];

        while (ld_acq(&flg[0]) < 8) {}      // chunk 0 of my batch ready
        float pre = out[base + col];
        for (int t = 0; t < TLEN; ++t) {
            const int nb = (t & 1) ^ 1;
            bar_sync_named(barid);          // red(t) complete
            float p0 = red[ 0*64 + col], p1 = red[ 1*64 + col];
            float p2 = red[ 2*64 + col], p3 = red[ 3*64 + col];
            float p4 = red[ 4*64 + col], p5 = red[ 5*64 + col];
            float p6 = red[ 6*64 + col], p7 = red[ 7*64 + col];
            float p8 = red[ 8*64 + col], p9 = red[ 9*64 + col];
            float pa = red[10*64 + col], pc = red[11*64 + col];
            float pd = red[12*64 + col], pe = red[13*64 + col];
            float pf = red[14*64 + col], pg = red[15*64 + col];
            float sum = (((p0+p1)+(p2+p3)) + ((p4+p5)+(p6+p7)))
                      + (((p8+p9)+(pa+pc)) + ((pd+pe)+(pf+pg)));
            const float hv = fast_tanh(sum + pre);
            if (t + 1 < TLEN) {
                const u32 bloc = mbX + (u32)nb * 8u;
                if (doExpect) mbar_expect_tx(bloc, CLSZ * 64 * 4);   // 2048 B
                const u32 val  = __float_as_uint(hv);
                const u32 dloc = hXa + (u32)nb * (HDIM * 4) + (u32)(rank * 64 + col) * 4;
                #pragma unroll
                for (int r = 0; r < CLSZ; r++)
                    st_async32(mapa32(dloc, (u32)r), val, mapa32(bloc, (u32)r));
                out[base + (long)t * HDIM + col] = hv;
                if (((t + 1) & 127) == 0) {             // next chunk gate
                    while (ld_acq(&flg[(t + 1) >> 7]) < 8) {}
                }
                pre = out[base + (long)(t + 1) * HDIM + col];
            } else {
                out[base + (long)t * HDIM + col] = hv;
            }
        }
    }
    cluster_sync_();
    // reset this cluster's 2 batches' flags for the next graph replay
    if (rank == 0 && tid < 32) g_flags[cl * 32 + tid] = 0;
}

// ---------------- launch ----------------
extern "C" void kernel_launch(void* const* d_in, const int* in_sizes, int n_in,
                              void* d_out, int out_size) {
    (void)in_sizes; (void)n_in; (void)out_size;
    const float* x    = (const float*)d_in[0];
    const float* Wxh  = (const float*)d_in[1];
    const float* Whh  = (const float*)d_in[2];
    const float* bias = (const float*)d_in[3];
    float* out = (float*)d_out;   // d_in[4] = A: backward-only, unused

    fused_rnn<<<GRID, NTHREADS>>>(x, Wxh, bias, Whh, out);
}

// round 16
// speedup vs baseline: 1.0181x; 1.0181x over previous
#include <cuda_runtime.h>
#include <cstdint>

#define HDIM   512
#define TLEN   2048
#define NBATCH 16
#define CLSZ   8
#define NCLUSTER (NBATCH / 2)       // 8 clusters, 2 batches each
#define NTHREADS 640                // 16 producer warps + 4 finisher warps
#define BARCNT   576                // 512 producers + 64 finisher threads

typedef unsigned long long u64;
typedef unsigned int u32;

// ---------------- PTX helpers ----------------
__device__ __forceinline__ u32 smem_u32(const void* p) {
    u32 a;
    asm("{ .reg .u64 t; cvta.to.shared.u64 t, %1; cvt.u32.u64 %0, t; }" : "=r"(a) : "l"(p));
    return a;
}
__device__ __forceinline__ void fma2(u64& d, u64 a, u64 b) {
    asm("fma.rn.f32x2 %0, %1, %2, %0;" : "+l"(d) : "l"(a), "l"(b));
}
__device__ __forceinline__ u64 pk2(float lo, float hi) {
    u64 r; asm("mov.b64 %0, {%1, %2};" : "=l"(r) : "f"(lo), "f"(hi)); return r;
}
__device__ __forceinline__ float lo32(u64 v) { return __uint_as_float((u32)(v & 0xffffffffull)); }
__device__ __forceinline__ float hi32(u64 v) { return __uint_as_float((u32)(v >> 32)); }
__device__ __forceinline__ u32 mapa32(u32 a, u32 r) {
    u32 d; asm("mapa.shared::cluster.u32 %0, %1, %2;" : "=r"(d) : "r"(a), "r"(r)); return d;
}
__device__ __forceinline__ void st_async32(u32 ra, u32 v, u32 rb) {
    asm volatile("st.async.shared::cluster.mbarrier::complete_tx::bytes.b32 [%0], %1, [%2];"
                 :: "r"(ra), "r"(v), "r"(rb) : "memory");
}
__device__ __forceinline__ void mbar_init(u32 m, u32 cnt) {
    asm volatile("mbarrier.init.shared.b64 [%0], %1;" :: "r"(m), "r"(cnt) : "memory");
}
__device__ __forceinline__ void mbar_expect_tx(u32 m, u32 bytes) {
    asm volatile("mbarrier.arrive.expect_tx.shared.b64 _, [%0], %1;" :: "r"(m), "r"(bytes) : "memory");
}
__device__ __forceinline__ void mbar_wait_parity(u32 m, u32 parity) {
    asm volatile(
        "{\n\t.reg .pred P;\nLW_%=:\n\t"
        "mbarrier.try_wait.parity.acquire.cluster.shared::cta.b64 P, [%0], %1, 0x989680;\n\t"
        "@!P bra LW_%=;\n\t}"
        :: "r"(m), "r"(parity) : "memory");
}
__device__ __forceinline__ void cluster_sync_() {
    asm volatile("barrier.cluster.arrive.aligned;" ::: "memory");
    asm volatile("barrier.cluster.wait.aligned;" ::: "memory");
}
__device__ __forceinline__ void bar_arrive(int id) {
    asm volatile("bar.arrive %0, %1;" :: "r"(id), "r"(BARCNT) : "memory");
}
__device__ __forceinline__ void bar_sync_named(int id) {
    asm volatile("bar.sync %0, %1;" :: "r"(id), "r"(BARCNT) : "memory");
}
// tanh(x) = sign(x)*(1-e)/(1+e), e = exp2(-2x*log2e), ~1e-7 abs err
__device__ __forceinline__ float fast_tanh(float x) {
    float ax = fabsf(x);
    float e;
    asm("ex2.approx.ftz.f32 %0, %1;" : "=f"(e) : "f"(ax * -2.885390082f));
    float r;
    asm("rcp.approx.ftz.f32 %0, %1;" : "=f"(r) : "f"(1.0f + e));
    return copysignf((1.0f - e) * r, x);
}

// ---------------- Phase 1: pre = X @ W_xh + b  (M=32768, N=512, K=512) ----------------
// f32x2 packed along N: A duplicated (a,a) at smem-store time into u64 As2;
// B pairs (b_n,b_n+1) come free from contiguous smem. Inner loop: 16 FMA2 + 5 LDS
// per k (vs 32 FFMA + 6 LDS scalar). Accumulation order per element unchanged
// -> bitwise-identical result to the scalar version.
__global__ __launch_bounds__(256) void pre_gemm(
    const float* __restrict__ X, const float* __restrict__ W,
    const float* __restrict__ bias, float* __restrict__ P)
{
    __shared__ __align__(16) u64   As2[16][130];   // [k][m], (a,a) duplicated
    __shared__ __align__(16) float Bs[16][64];     // [k][n]
    const int tid = threadIdx.x;
    const int tx  = tid & 15;
    const int ty  = tid >> 4;
    const int m0  = blockIdx.x * 128;
    const int n0  = blockIdx.y * 64;
    const int arow = tid >> 1;
    const int ak   = (tid & 1) * 8;
    const int bk   = tid >> 4;
    const int bn   = (tid & 15) * 4;

    u64 acc[8][2];   // [m][n-pair]: lo = col n, hi = col n+1
    #pragma unroll
    for (int i = 0; i < 8; i++) { acc[i][0] = 0ull; acc[i][1] = 0ull; }

    for (int kb = 0; kb < 32; kb++) {
        const int k0 = kb * 16;
        const float* Xp = X + (long)(m0 + arow) * HDIM + k0 + ak;
        float4 a0 = *(const float4*)Xp;
        float4 a1 = *(const float4*)(Xp + 4);
        float4 bv = *(const float4*)(W + (long)(k0 + bk) * HDIM + n0 + bn);
        As2[ak+0][arow] = pk2(a0.x, a0.x); As2[ak+1][arow] = pk2(a0.y, a0.y);
        As2[ak+2][arow] = pk2(a0.z, a0.z); As2[ak+3][arow] = pk2(a0.w, a0.w);
        As2[ak+4][arow] = pk2(a1.x, a1.x); As2[ak+5][arow] = pk2(a1.y, a1.y);
        As2[ak+6][arow] = pk2(a1.z, a1.z); As2[ak+7][arow] = pk2(a1.w, a1.w);
        *(float4*)&Bs[bk][bn] = bv;
        __syncthreads();
        #pragma unroll
        for (int k = 0; k < 16; k++) {
            ulonglong2 b2  = *(const ulonglong2*)&Bs[k][tx * 4];  // (bn,bn+1),(bn+2,bn+3)
            const u64* ap  = &As2[k][ty * 8];
            ulonglong2 a01 = *(const ulonglong2*)(ap + 0);
            ulonglong2 a23 = *(const ulonglong2*)(ap + 2);
            ulonglong2 a45 = *(const ulonglong2*)(ap + 4);
            ulonglong2 a67 = *(const ulonglong2*)(ap + 6);
            fma2(acc[0][0], a01.x, b2.x); fma2(acc[0][1], a01.x, b2.y);
            fma2(acc[1][0], a01.y, b2.x); fma2(acc[1][1], a01.y, b2.y);
            fma2(acc[2][0], a23.x, b2.x); fma2(acc[2][1], a23.x, b2.y);
            fma2(acc[3][0], a23.y, b2.x); fma2(acc[3][1], a23.y, b2.y);
            fma2(acc[4][0], a45.x, b2.x); fma2(acc[4][1], a45.x, b2.y);
            fma2(acc[5][0], a45.y, b2.x); fma2(acc[5][1], a45.y, b2.y);
            fma2(acc[6][0], a67.x, b2.x); fma2(acc[6][1], a67.x, b2.y);
            fma2(acc[7][0], a67.y, b2.x); fma2(acc[7][1], a67.y, b2.y);
        }
        __syncthreads();
    }
    float4 bb = *(const float4*)(bias + n0 + tx * 4);
    #pragma unroll
    for (int i = 0; i < 8; i++) {
        float4 o;
        o.x = lo32(acc[i][0]) + bb.x; o.y = hi32(acc[i][0]) + bb.y;
        o.z = lo32(acc[i][1]) + bb.z; o.w = hi32(acc[i][1]) + bb.w;
        *(float4*)&P[(long)(m0 + ty * 8 + i) * HDIM + n0 + tx * 4] = o;
    }
}

// ---------------- Phase 2: scan — byte-for-byte R14 (measured 1371 us) ----------------
__global__ __launch_bounds__(NTHREADS, 1) __cluster_dims__(CLSZ, 1, 1)
void rnn_scan(const float* __restrict__ Whh, float* __restrict__ out)
{
    __shared__ __align__(16) float hA[2][HDIM];
    __shared__ __align__(16) float hB[2][HDIM];
    __shared__ __align__(16) float redA[16][64];
    __shared__ __align__(16) float redB[16][64];
    __shared__ __align__(16) u64 mbar[4];   // [0,1]=A ph0/1, [2,3]=B ph0/1

    const int tid  = threadIdx.x;
    const int wi   = tid >> 5;
    const int lane = tid & 31;
    const int rank = blockIdx.x & (CLSZ - 1);
    const int cl   = blockIdx.x / CLSZ;

    for (int i = tid; i < 2 * HDIM; i += NTHREADS) {
        ((float*)hA)[i] = 0.0f;
        ((float*)hB)[i] = 0.0f;
    }
    const u32 hAa = smem_u32(&hA[0][0]);
    const u32 hBa = smem_u32(&hB[0][0]);
    const u32 mb0 = smem_u32(&mbar[0]);
    if (tid == 0) {
        mbar_init(mb0,      1);
        mbar_init(mb0 + 8,  1);
        mbar_init(mb0 + 16, 1);
        mbar_init(mb0 + 24, 1);
        asm volatile("fence.mbarrier_init.release.cluster;" ::: "memory");
    }
    __syncthreads();
    cluster_sync_();

    const long baseA = (long)(2 * cl)     * TLEN * HDIM + rank * 64;
    const long baseB = (long)(2 * cl + 1) * TLEN * HDIM + rank * 64;

    if (wi < 16) {
        // ================= producers =================
        const int jg = tid & 15;     // 4-col group
        const int kc = tid >> 4;     // 16-k chunk (0..31)
        u64 w[4][8];
        {
            const int j0 = rank * 64 + jg * 4;
            const int kb = kc * 16;
            #pragma unroll
            for (int p = 0; p < 8; p++) {
                float4 l4 = *(const float4*)(Whh + (kb + 2*p)     * HDIM + j0);
                float4 h4 = *(const float4*)(Whh + (kb + 2*p + 1) * HDIM + j0);
                w[0][p] = pk2(l4.x, h4.x);
                w[1][p] = pk2(l4.y, h4.y);
                w[2][p] = pk2(l4.z, h4.z);
                w[3][p] = pk2(l4.w, h4.w);
            }
        }
        for (int t = 0; t < TLEN; ++t) {
            const int pb = t & 1;
            const u32 par = (u32)(((t - 2 + pb) >> 1) & 1);

            if (t > 0) mbar_wait_parity(mb0 + (u32)pb * 8u, par);      // A ready
            {
                const ulonglong2* hp = (const ulonglong2*)&hA[pb][kc * 16];
                u64 a0 = 0ull, a1 = 0ull, a2 = 0ull, a3 = 0ull;
                #pragma unroll
                for (int p = 0; p < 4; p++) {
                    ulonglong2 hv = hp[p];
                    fma2(a0, hv.x, w[0][2*p]);   fma2(a1, hv.x, w[1][2*p]);
                    fma2(a2, hv.x, w[2][2*p]);   fma2(a3, hv.x, w[3][2*p]);
                    fma2(a0, hv.y, w[0][2*p+1]); fma2(a1, hv.y, w[1][2*p+1]);
                    fma2(a2, hv.y, w[2][2*p+1]); fma2(a3, hv.y, w[3][2*p+1]);
                }
                float s0 = lo32(a0) + hi32(a0);
                float s1 = lo32(a1) + hi32(a1);
                float s2 = lo32(a2) + hi32(a2);
                float s3 = lo32(a3) + hi32(a3);
                s0 += __shfl_down_sync(0xffffffffu, s0, 16);
                s1 += __shfl_down_sync(0xffffffffu, s1, 16);
                s2 += __shfl_down_sync(0xffffffffu, s2, 16);
                s3 += __shfl_down_sync(0xffffffffu, s3, 16);
                if (lane < 16) {
                    float4 v; v.x = s0; v.y = s1; v.z = s2; v.w = s3;
                    *(float4*)&redA[wi][jg * 4] = v;
                }
            }
            bar_arrive(1);

            if (t > 0) mbar_wait_parity(mb0 + 16u + (u32)pb * 8u, par); // B ready
            {
                const ulonglong2* hp = (const ulonglong2*)&hB[pb][kc * 16];
                u64 a0 = 0ull, a1 = 0ull, a2 = 0ull, a3 = 0ull;
                #pragma unroll
                for (int p = 0; p < 4; p++) {
                    ulonglong2 hv = hp[p];
                    fma2(a0, hv.x, w[0][2*p]);   fma2(a1, hv.x, w[1][2*p]);
                    fma2(a2, hv.x, w[2][2*p]);   fma2(a3, hv.x, w[3][2*p]);
                    fma2(a0, hv.y, w[0][2*p+1]); fma2(a1, hv.y, w[1][2*p+1]);
                    fma2(a2, hv.y, w[2][2*p+1]); fma2(a3, hv.y, w[3][2*p+1]);
                }
                float s0 = lo32(a0) + hi32(a0);
                float s1 = lo32(a1) + hi32(a1);
                float s2 = lo32(a2) + hi32(a2);
                float s3 = lo32(a3) + hi32(a3);
                s0 += __shfl_down_sync(0xffffffffu, s0, 16);
                s1 += __shfl_down_sync(0xffffffffu, s1, 16);
                s2 += __shfl_down_sync(0xffffffffu, s2, 16);
                s3 += __shfl_down_sync(0xffffffffu, s3, 16);
                if (lane < 16) {
                    float4 v; v.x = s0; v.y = s1; v.z = s2; v.w = s3;
                    *(float4*)&redB[wi][jg * 4] = v;
                }
            }
            bar_arrive(2);
        }
    } else {
        // ================= finishers =================
        const int wf    = wi - 16;          // 0,1 = batch A; 2,3 = batch B
        const int isB   = wf >> 1;
        const long base = isB ? baseB : baseA;
        const u32 hXa   = isB ? hBa : hAa;
        const u32 mbX   = mb0 + (isB ? 16u : 0u);
        const int barid = isB ? 2 : 1;
        const float* red = isB ? &redB[0][0] : &redA[0][0];
        const int col   = (wf & 1) * 32 + lane;   // one column per lane
        const int doExpect = ((wf & 1) == 0) && (lane == 0);

        float pre = out[base + col];
        for (int t = 0; t < TLEN; ++t) {
            const int nb = (t & 1) ^ 1;
            bar_sync_named(barid);          // red(t) complete
            float p0 = red[ 0*64 + col], p1 = red[ 1*64 + col];
            float p2 = red[ 2*64 + col], p3 = red[ 3*64 + col];
            float p4 = red[ 4*64 + col], p5 = red[ 5*64 + col];
            float p6 = red[ 6*64 + col], p7 = red[ 7*64 + col];
            float p8 = red[ 8*64 + col], p9 = red[ 9*64 + col];
            float pa = red[10*64 + col], pc = red[11*64 + col];
            float pd = red[12*64 + col], pe = red[13*64 + col];
            float pf = red[14*64 + col], pg = red[15*64 + col];
            float sum = (((p0+p1)+(p2+p3)) + ((p4+p5)+(p6+p7)))
                      + (((p8+p9)+(pa+pc)) + ((pd+pe)+(pf+pg)));
            const float hv = fast_tanh(sum + pre);
            if (t + 1 < TLEN) {
                const u32 bloc = mbX + (u32)nb * 8u;
                if (doExpect) mbar_expect_tx(bloc, CLSZ * 64 * 4);   // 2048 B
                const u32 val  = __float_as_uint(hv);
                const u32 dloc = hXa + (u32)nb * (HDIM * 4) + (u32)(rank * 64 + col) * 4;
                #pragma unroll
                for (int r = 0; r < CLSZ; r++)
                    st_async32(mapa32(dloc, (u32)r), val, mapa32(bloc, (u32)r));
                out[base + (long)t * HDIM + col] = hv;
                pre = out[base + (long)(t + 1) * HDIM + col];
            } else {
                out[base + (long)t * HDIM + col] = hv;
            }
        }
    }
    cluster_sync_();
}

// ---------------- launch ----------------
extern "C" void kernel_launch(void* const* d_in, const int* in_sizes, int n_in,
                              void* d_out, int out_size) {
    (void)in_sizes; (void)n_in; (void)out_size;
    const float* x    = (const float*)d_in[0];
    const float* Wxh  = (const float*)d_in[1];
    const float* Whh  = (const float*)d_in[2];
    const float* bias = (const float*)d_in[3];
    float* out = (float*)d_out;   // d_in[4] = A: backward-only, unused

    dim3 g1(NBATCH * TLEN / 128, HDIM / 64);
    pre_gemm<<<g1, 256>>>(x, Wxh, bias, out);            // pre (+bias) into out
    rnn_scan<<<NCLUSTER * CLSZ, NTHREADS>>>(Whh, out);   // in-place scan
}

// round 17
// speedup vs baseline: 1.0545x; 1.0357x over previous
#include <cuda_runtime.h>
#include <cstdint>

#define HDIM   512
#define TLEN   2048
#define NBATCH 16
#define CLSZ   8
#define NCLUSTER (NBATCH / 2)       // 8 clusters, 2 batches each
#define NTHREADS 640                // 16 producer warps + 4 finisher warps
#define BARCNT   576                // 512 producers + 64 finisher threads

typedef unsigned long long u64;
typedef unsigned int u32;

// ---------------- PTX helpers ----------------
__device__ __forceinline__ u32 smem_u32(const void* p) {
    u32 a;
    asm("{ .reg .u64 t; cvta.to.shared.u64 t, %1; cvt.u32.u64 %0, t; }" : "=r"(a) : "l"(p));
    return a;
}
__device__ __forceinline__ void fma2(u64& d, u64 a, u64 b) {
    asm("fma.rn.f32x2 %0, %1, %2, %0;" : "+l"(d) : "l"(a), "l"(b));
}
__device__ __forceinline__ void add2(u64& d, u64 a, u64 b) {
    asm("add.rn.f32x2 %0, %1, %2;" : "=l"(d) : "l"(a), "l"(b));
}
__device__ __forceinline__ u64 pk2(float lo, float hi) {
    u64 r; asm("mov.b64 %0, {%1, %2};" : "=l"(r) : "f"(lo), "f"(hi)); return r;
}
__device__ __forceinline__ float lo32(u64 v) { return __uint_as_float((u32)(v & 0xffffffffull)); }
__device__ __forceinline__ float hi32(u64 v) { return __uint_as_float((u32)(v >> 32)); }
__device__ __forceinline__ u32 mapa32(u32 a, u32 r) {
    u32 d; asm("mapa.shared::cluster.u32 %0, %1, %2;" : "=r"(d) : "r"(a), "r"(r)); return d;
}
__device__ __forceinline__ void st_async32(u32 ra, u32 v, u32 rb) {
    asm volatile("st.async.shared::cluster.mbarrier::complete_tx::bytes.b32 [%0], %1, [%2];"
                 :: "r"(ra), "r"(v), "r"(rb) : "memory");
}
__device__ __forceinline__ void mbar_init(u32 m, u32 cnt) {
    asm volatile("mbarrier.init.shared.b64 [%0], %1;" :: "r"(m), "r"(cnt) : "memory");
}
__device__ __forceinline__ void mbar_expect_tx(u32 m, u32 bytes) {
    asm volatile("mbarrier.arrive.expect_tx.shared.b64 _, [%0], %1;" :: "r"(m), "r"(bytes) : "memory");
}
__device__ __forceinline__ void mbar_wait_parity(u32 m, u32 parity) {
    asm volatile(
        "{\n\t.reg .pred P;\nLW_%=:\n\t"
        "mbarrier.try_wait.parity.acquire.cluster.shared::cta.b64 P, [%0], %1, 0x989680;\n\t"
        "@!P bra LW_%=;\n\t}"
        :: "r"(m), "r"(parity) : "memory");
}
__device__ __forceinline__ void cluster_sync_() {
    asm volatile("barrier.cluster.arrive.aligned;" ::: "memory");
    asm volatile("barrier.cluster.wait.aligned;" ::: "memory");
}
__device__ __forceinline__ void bar_arrive(int id) {
    asm volatile("bar.arrive %0, %1;" :: "r"(id), "r"(BARCNT) : "memory");
}
__device__ __forceinline__ void bar_sync_named(int id) {
    asm volatile("bar.sync %0, %1;" :: "r"(id), "r"(BARCNT) : "memory");
}
// tanh(x) = sign(x)*(1-e)/(1+e), e = exp2(-2x*log2e), ~1e-7 abs err
__device__ __forceinline__ float fast_tanh(float x) {
    float ax = fabsf(x);
    float e;
    asm("ex2.approx.ftz.f32 %0, %1;" : "=f"(e) : "f"(ax * -2.885390082f));
    float r;
    asm("rcp.approx.ftz.f32 %0, %1;" : "=f"(r) : "f"(1.0f + e));
    return copysignf((1.0f - e) * r, x);
}

// ---------------- Phase 1: pre = X @ W_xh + b  (M=32768, N=512, K=512) ----------------
// R14 scalar version (known 382us — f32x2 variants measured SLOWER: FFMA2 is
// ~half-rate per element on the fma pipe, no throughput win on a GEMM).
__global__ __launch_bounds__(256) void pre_gemm(
    const float* __restrict__ X, const float* __restrict__ W,
    const float* __restrict__ bias, float* __restrict__ P)
{
    __shared__ __align__(16) float As[16][130];
    __shared__ __align__(16) float Bs[16][64];
    const int tid = threadIdx.x;
    const int tx  = tid & 15;
    const int ty  = tid >> 4;
    const int m0  = blockIdx.x * 128;
    const int n0  = blockIdx.y * 64;
    const int arow = tid >> 1;
    const int ak   = (tid & 1) * 8;
    const int bk   = tid >> 4;
    const int bn   = (tid & 15) * 4;

    float acc[8][4];
    #pragma unroll
    for (int i = 0; i < 8; i++)
        #pragma unroll
        for (int j = 0; j < 4; j++) acc[i][j] = 0.0f;

    for (int kb = 0; kb < 32; kb++) {
        const int k0 = kb * 16;
        const float* Xp = X + (long)(m0 + arow) * HDIM + k0 + ak;
        float4 a0 = *(const float4*)Xp;
        float4 a1 = *(const float4*)(Xp + 4);
        float4 bv = *(const float4*)(W + (long)(k0 + bk) * HDIM + n0 + bn);
        As[ak+0][arow] = a0.x; As[ak+1][arow] = a0.y; As[ak+2][arow] = a0.z; As[ak+3][arow] = a0.w;
        As[ak+4][arow] = a1.x; As[ak+5][arow] = a1.y; As[ak+6][arow] = a1.z; As[ak+7][arow] = a1.w;
        *(float4*)&Bs[bk][bn] = bv;
        __syncthreads();
        #pragma unroll
        for (int k = 0; k < 16; k++) {
            float4 rb = *(const float4*)&Bs[k][tx * 4];
            float ra[8];
            #pragma unroll
            for (int i = 0; i < 4; i++) {
                float2 t2 = *(const float2*)&As[k][ty * 8 + 2 * i];
                ra[2*i] = t2.x; ra[2*i+1] = t2.y;
            }
            #pragma unroll
            for (int i = 0; i < 8; i++) {
                acc[i][0] += ra[i] * rb.x;
                acc[i][1] += ra[i] * rb.y;
                acc[i][2] += ra[i] * rb.z;
                acc[i][3] += ra[i] * rb.w;
            }
        }
        __syncthreads();
    }
    float4 bb = *(const float4*)(bias + n0 + tx * 4);
    #pragma unroll
    for (int i = 0; i < 8; i++) {
        float4 o;
        o.x = acc[i][0] + bb.x; o.y = acc[i][1] + bb.y;
        o.z = acc[i][2] + bb.z; o.w = acc[i][3] + bb.w;
        *(float4*)&P[(long)(m0 + ty * 8 + i) * HDIM + n0 + tx * 4] = o;
    }
}

// ---------------- Phase 2: scan — packed partials, no producer shfl ----------------
// vs R14: producers store their 4 packed u64 accumulators directly (2x STS.128,
// no lo/hi unpack, no shfl) -> per-phase instr 54->40 and dependent tail
// ~40cyc->~5cyc. Finishers now sum 32 packed partials (conflict-free LDS.64,
// pipelined add2 tree) and unpack once. Hazard chains identical to R14.
__global__ __launch_bounds__(NTHREADS, 1) __cluster_dims__(CLSZ, 1, 1)
void rnn_scan(const float* __restrict__ Whh, float* __restrict__ out)
{
    __shared__ __align__(16) float hA[2][HDIM];
    __shared__ __align__(16) float hB[2][HDIM];
    __shared__ __align__(16) u64 redA[32][64];   // [kc][col], packed (evenK,oddK)
    __shared__ __align__(16) u64 redB[32][64];
    __shared__ __align__(16) u64 mbar[4];        // [0,1]=A ph0/1, [2,3]=B ph0/1

    const int tid  = threadIdx.x;
    const int wi   = tid >> 5;
    const int lane = tid & 31;
    const int rank = blockIdx.x & (CLSZ - 1);
    const int cl   = blockIdx.x / CLSZ;

    for (int i = tid; i < 2 * HDIM; i += NTHREADS) {
        ((float*)hA)[i] = 0.0f;
        ((float*)hB)[i] = 0.0f;
    }
    const u32 hAa = smem_u32(&hA[0][0]);
    const u32 hBa = smem_u32(&hB[0][0]);
    const u32 mb0 = smem_u32(&mbar[0]);
    if (tid == 0) {
        mbar_init(mb0,      1);
        mbar_init(mb0 + 8,  1);
        mbar_init(mb0 + 16, 1);
        mbar_init(mb0 + 24, 1);
        asm volatile("fence.mbarrier_init.release.cluster;" ::: "memory");
    }
    __syncthreads();
    cluster_sync_();

    const long baseA = (long)(2 * cl)     * TLEN * HDIM + rank * 64;
    const long baseB = (long)(2 * cl + 1) * TLEN * HDIM + rank * 64;

    if (wi < 16) {
        // ================= producers =================
        const int jg = tid & 15;     // 4-col group
        const int kc = tid >> 4;     // 16-k chunk (0..31)
        u64 w[4][8];
        {
            const int j0 = rank * 64 + jg * 4;
            const int kb = kc * 16;
            #pragma unroll
            for (int p = 0; p < 8; p++) {
                float4 l4 = *(const float4*)(Whh + (kb + 2*p)     * HDIM + j0);
                float4 h4 = *(const float4*)(Whh + (kb + 2*p + 1) * HDIM + j0);
                w[0][p] = pk2(l4.x, h4.x);
                w[1][p] = pk2(l4.y, h4.y);
                w[2][p] = pk2(l4.z, h4.z);
                w[3][p] = pk2(l4.w, h4.w);
            }
        }
        for (int t = 0; t < TLEN; ++t) {
            const int pb = t & 1;
            const u32 par = (u32)(((t - 2 + pb) >> 1) & 1);

            if (t > 0) mbar_wait_parity(mb0 + (u32)pb * 8u, par);      // A ready
            {
                const ulonglong2* hp = (const ulonglong2*)&hA[pb][kc * 16];
                u64 a0 = 0ull, a1 = 0ull, a2 = 0ull, a3 = 0ull;
                #pragma unroll
                for (int p = 0; p < 4; p++) {
                    ulonglong2 hv = hp[p];
                    fma2(a0, hv.x, w[0][2*p]);   fma2(a1, hv.x, w[1][2*p]);
                    fma2(a2, hv.x, w[2][2*p]);   fma2(a3, hv.x, w[3][2*p]);
                    fma2(a0, hv.y, w[0][2*p+1]); fma2(a1, hv.y, w[1][2*p+1]);
                    fma2(a2, hv.y, w[2][2*p+1]); fma2(a3, hv.y, w[3][2*p+1]);
                }
                ulonglong2 v01; v01.x = a0; v01.y = a1;
                ulonglong2 v23; v23.x = a2; v23.y = a3;
                *(ulonglong2*)&redA[kc][jg * 4]     = v01;
                *(ulonglong2*)&redA[kc][jg * 4 + 2] = v23;
            }
            bar_arrive(1);

            if (t > 0) mbar_wait_parity(mb0 + 16u + (u32)pb * 8u, par); // B ready
            {
                const ulonglong2* hp = (const ulonglong2*)&hB[pb][kc * 16];
                u64 a0 = 0ull, a1 = 0ull, a2 = 0ull, a3 = 0ull;
                #pragma unroll
                for (int p = 0; p < 4; p++) {
                    ulonglong2 hv = hp[p];
                    fma2(a0, hv.x, w[0][2*p]);   fma2(a1, hv.x, w[1][2*p]);
                    fma2(a2, hv.x, w[2][2*p]);   fma2(a3, hv.x, w[3][2*p]);
                    fma2(a0, hv.y, w[0][2*p+1]); fma2(a1, hv.y, w[1][2*p+1]);
                    fma2(a2, hv.y, w[2][2*p+1]); fma2(a3, hv.y, w[3][2*p+1]);
                }
                ulonglong2 v01; v01.x = a0; v01.y = a1;
                ulonglong2 v23; v23.x = a2; v23.y = a3;
                *(ulonglong2*)&redB[kc][jg * 4]     = v01;
                *(ulonglong2*)&redB[kc][jg * 4 + 2] = v23;
            }
            bar_arrive(2);
        }
    } else {
        // ================= finishers =================
        const int wf    = wi - 16;          // 0,1 = batch A; 2,3 = batch B
        const int isB   = wf >> 1;
        const long base = isB ? baseB : baseA;
        const u32 hXa   = isB ? hBa : hAa;
        const u32 mbX   = mb0 + (isB ? 16u : 0u);
        const int barid = isB ? 2 : 1;
        const u64* red  = isB ? &redB[0][0] : &redA[0][0];
        const int col   = (wf & 1) * 32 + lane;   // one column per lane
        const int doExpect = ((wf & 1) == 0) && (lane == 0);
        const u64* rp   = red + col;              // stride 64 u64 per kc row

        float pre = out[base + col];
        for (int t = 0; t < TLEN; ++t) {
            const int nb = (t & 1) ^ 1;
            bar_sync_named(barid);          // red(t) complete
            u64 q[8];
            #pragma unroll
            for (int g = 0; g < 8; g++) {
                u64 x0 = rp[(4*g + 0) * 64], x1 = rp[(4*g + 1) * 64];
                u64 x2 = rp[(4*g + 2) * 64], x3 = rp[(4*g + 3) * 64];
                u64 t0, t1;
                add2(t0, x0, x1); add2(t1, x2, x3); add2(q[g], t0, t1);
            }
            u64 r0, r1, r2, r3, r4, r5, rr;
            add2(r0, q[0], q[1]); add2(r1, q[2], q[3]);
            add2(r2, q[4], q[5]); add2(r3, q[6], q[7]);
            add2(r4, r0, r1); add2(r5, r2, r3); add2(rr, r4, r5);
            const float sum = lo32(rr) + hi32(rr);
            const float hv = fast_tanh(sum + pre);
            if (t + 1 < TLEN) {
                const u32 bloc = mbX + (u32)nb * 8u;
                if (doExpect) mbar_expect_tx(bloc, CLSZ * 64 * 4);   // 2048 B
                const u32 val  = __float_as_uint(hv);
                const u32 dloc = hXa + (u32)nb * (HDIM * 4) + (u32)(rank * 64 + col) * 4;
                #pragma unroll
                for (int r = 0; r < CLSZ; r++)
                    st_async32(mapa32(dloc, (u32)r), val, mapa32(bloc, (u32)r));
                out[base + (long)t * HDIM + col] = hv;
                pre = out[base + (long)(t + 1) * HDIM + col];
            } else {
                out[base + (long)t * HDIM + col] = hv;
            }
        }
    }
    cluster_sync_();
}

// ---------------- launch ----------------
extern "C" void kernel_launch(void* const* d_in, const int* in_sizes, int n_in,
                              void* d_out, int out_size) {
    (void)in_sizes; (void)n_in; (void)out_size;
    const float* x    = (const float*)d_in[0];
    const float* Wxh  = (const float*)d_in[1];
    const float* Whh  = (const float*)d_in[2];
    const float* bias = (const float*)d_in[3];
    float* out = (float*)d_out;   // d_in[4] = A: backward-only, unused

    dim3 g1(NBATCH * TLEN / 128, HDIM / 64);
    pre_gemm<<<g1, 256>>>(x, Wxh, bias, out);            // pre (+bias) into out
    rnn_scan<<<NCLUSTER * CLSZ, NTHREADS>>>(Whh, out);   // in-place scan
}